// round 2
// baseline (speedup 1.0000x reference)
#include <cuda_runtime.h>
#include <cstddef>

// Problem constants
#define BB 16
#define CC 256
#define HH 64
#define WW 64
#define DD 4          // max displacement
#define PP 9          // patch = 2*DD+1

// Tiling
#define TI 4          // rows per block tile
#define KC 8          // channels staged per chunk
#define XS 66         // x smem row stride (floats), S8=33 -> conflict-free LDS.64
#define YR (TI + 2*DD)   // 12 y rows per tile
#define YS 74         // y smem row stride (floats), S8=37 -> conflict-free LDS.64

#define NTHREADS 288  // 9 warps: warp w -> di = w

__global__ __launch_bounds__(NTHREADS, 2)
void corr_kernel(const float* __restrict__ x,
                 const float* __restrict__ y,
                 float* __restrict__ out)
{
    __shared__ float xs[KC * TI * XS];   // 8*4*66  = 2112 floats
    __shared__ float ys[KC * YR * YS];   // 8*12*74 = 7104 floats  (total ~36 KB)

    const int bx   = blockIdx.x;
    const int b    = bx >> 4;            // / 16
    const int i0   = (bx & 15) * TI;     // row-group origin
    const int tid  = threadIdx.x;
    const int di   = tid >> 5;           // warp id == displacement row 0..8
    const int lane = tid & 31;
    const int r    = lane & 3;           // local row 0..3
    const int jseg = (lane >> 2) * 8;    // 8-wide column segment 0,8,...,56

    float acc[8][PP];
    #pragma unroll
    for (int k = 0; k < 8; ++k)
        #pragma unroll
        for (int d = 0; d < PP; ++d)
            acc[k][d] = 0.0f;

    const float* xb = x + (size_t)b * CC * HH * WW;
    const float* yb = y + (size_t)b * CC * HH * WW;

    for (int c0 = 0; c0 < CC; c0 += KC) {
        __syncthreads();
        // ---- stage x chunk: KC x TI x 64, rows fully coalesced ----
        for (int idx = tid; idx < KC * TI * WW; idx += NTHREADS) {
            int c   = idx >> 8;          // / (TI*WW) = 256
            int rem = idx & 255;
            int rr  = rem >> 6;
            int col = rem & 63;
            xs[c * (TI * XS) + rr * XS + col] =
                xb[(size_t)(c0 + c) * HH * WW + (i0 + rr) * WW + col];
        }
        // ---- stage y chunk: KC x YR x 72 (zero-padded halo) ----
        for (int idx = tid; idx < KC * YR * 72; idx += NTHREADS) {
            int c   = idx / (YR * 72);
            int rem = idx - c * (YR * 72);
            int q   = rem / 72;
            int t   = rem - q * 72;
            int gi  = i0 + q - DD;
            int gj  = t - DD;
            float v = 0.0f;
            if (gi >= 0 && gi < HH && gj >= 0 && gj < WW)
                v = yb[(size_t)(c0 + c) * HH * WW + gi * WW + gj];
            ys[c * (YR * YS) + q * YS + t] = v;
        }
        __syncthreads();

        // ---- compute: 72 FMAs per channel per thread ----
        #pragma unroll
        for (int c = 0; c < KC; ++c) {
            const float2* xr2 = reinterpret_cast<const float2*>(
                &xs[c * (TI * XS) + r * XS + jseg]);
            const float2* yr2 = reinterpret_cast<const float2*>(
                &ys[c * (YR * YS) + (r + di) * YS + jseg]);

            float xv[8], yv[16];
            #pragma unroll
            for (int m = 0; m < 4; ++m) {
                float2 v = xr2[m];
                xv[2 * m]     = v.x;
                xv[2 * m + 1] = v.y;
            }
            #pragma unroll
            for (int m = 0; m < 8; ++m) {
                float2 v = yr2[m];
                yv[2 * m]     = v.x;
                yv[2 * m + 1] = v.y;
            }
            #pragma unroll
            for (int k = 0; k < 8; ++k)
                #pragma unroll
                for (int d = 0; d < PP; ++d)
                    acc[k][d] += xv[k] * yv[k + d];
        }
    }

    // ---- write out: out[b, di*9+dj, i0+r, jseg..jseg+7] ----
    const float scale = 1.0f / (float)CC;
    #pragma unroll
    for (int d = 0; d < PP; ++d) {
        int ch = di * PP + d;
        float* o = out + (((size_t)b * (PP * PP) + ch) * HH + (i0 + r)) * WW + jseg;
        float4 v0, v1;
        v0.x = acc[0][d] * scale; v0.y = acc[1][d] * scale;
        v0.z = acc[2][d] * scale; v0.w = acc[3][d] * scale;
        v1.x = acc[4][d] * scale; v1.y = acc[5][d] * scale;
        v1.z = acc[6][d] * scale; v1.w = acc[7][d] * scale;
        reinterpret_cast<float4*>(o)[0] = v0;
        reinterpret_cast<float4*>(o)[1] = v1;
    }
}

extern "C" void kernel_launch(void* const* d_in, const int* in_sizes, int n_in,
                              void* d_out, int out_size)
{
    const float* x = (const float*)d_in[0];
    const float* y = (const float*)d_in[1];
    float* out = (float*)d_out;
    (void)in_sizes; (void)n_in; (void)out_size;

    dim3 grid(BB * (HH / TI));   // 16 * 16 = 256 blocks
    dim3 block(NTHREADS);        // 9 warps
    corr_kernel<<<grid, block>>>(x, y, out);
}

// round 4
// speedup vs baseline: 2.0594x; 2.0594x over previous
#include <cuda_runtime.h>
#include <cstdint>
#include <cstddef>

// Problem constants
#define BB 16
#define CC 256
#define HH 64
#define WW 64
#define HW (HH*WW)
#define DD 4          // max displacement
#define PP 9          // patch = 2d+1

// Tiling
#define TI 4          // rows per block tile
#define KC 8          // channels per staged chunk
#define NCHUNK (CC/KC)
#define XS 66         // x smem row stride (floats): f2-residue r*33 -> conflict-free
#define YR (TI + 2*DD)   // 12 y rows per tile
#define YS 74         // y smem row stride (floats): f2-residue (r+di)*37 -> conflict-free

#define NTH 288       // 9 warps; warp w == displacement row di

#define XSZ (KC*TI*XS)     // 2112 floats
#define YSZ (KC*YR*YS)     // 7104 floats
#define BUFSZ (XSZ+YSZ)    // 9216 floats per pipeline buffer
#define SMEM_BYTES (2*BUFSZ*4)   // 73728 B

__device__ __forceinline__ uint32_t s2u(const void* p) {
    return (uint32_t)__cvta_generic_to_shared(p);
}
__device__ __forceinline__ void cpa8(uint32_t s, const float* g) {
    asm volatile("cp.async.ca.shared.global [%0], [%1], 8;\n" :: "r"(s), "l"(g));
}
__device__ __forceinline__ void cp_commit() {
    asm volatile("cp.async.commit_group;\n");
}

// Issue cp.async for one 8-channel chunk into buffer sb. Shift/mask math only.
__device__ __forceinline__ void stage_chunk(float* sb,
                                            const float* __restrict__ xb,
                                            const float* __restrict__ yb,
                                            int c0, int i0, int tid, int vmask)
{
    // x: KC*TI*32 = 1024 float2 jobs, flat thread-strided
    for (int idx = tid; idx < KC * TI * 32; idx += NTH) {
        int c    = idx >> 7;
        int rr   = (idx >> 5) & 3;
        int col2 = idx & 31;
        uint32_t s = s2u(sb + c * (TI * XS) + rr * XS + col2 * 2);
        cpa8(s, xb + (size_t)(c0 + c) * HW + (i0 + rr) * WW + col2 * 2);
    }
    // y: 96 row-jobs (q-major: job = q*8 + c), one warp per job, 32 f2/row
    int w = tid >> 5, lane = tid & 31;
    for (int job = w; job < KC * YR; job += 9) {
        int q = job >> 3;
        int c = job & 7;
        if ((vmask >> q) & 1) {
            int gi = i0 + q - DD;
            uint32_t s = s2u(sb + XSZ + c * (YR * YS) + q * YS + DD + lane * 2);
            cpa8(s, yb + (size_t)(c0 + c) * HW + gi * WW + lane * 2);
        }
    }
}

__device__ __forceinline__ void compute_chunk(const float* sb, float acc[8][PP],
                                              int r, int di, int jseg)
{
    #pragma unroll
    for (int c = 0; c < KC; ++c) {
        const float2* xr2 = reinterpret_cast<const float2*>(
            sb + c * (TI * XS) + r * XS + jseg);
        const float2* yr2 = reinterpret_cast<const float2*>(
            sb + XSZ + c * (YR * YS) + (r + di) * YS + jseg);

        float xv[8], yv[16];
        #pragma unroll
        for (int m = 0; m < 4; ++m) {
            float2 v = xr2[m];
            xv[2 * m] = v.x; xv[2 * m + 1] = v.y;
        }
        #pragma unroll
        for (int m = 0; m < 8; ++m) {
            float2 v = yr2[m];
            yv[2 * m] = v.x; yv[2 * m + 1] = v.y;
        }
        #pragma unroll
        for (int k = 0; k < 8; ++k)
            #pragma unroll
            for (int d = 0; d < PP; ++d)
                acc[k][d] += xv[k] * yv[k + d];
    }
}

__global__ __launch_bounds__(NTH, 2)
void corr_kernel(const float* __restrict__ x,
                 const float* __restrict__ y,
                 float* __restrict__ out)
{
    extern __shared__ float smem[];   // [2][BUFSZ]

    const int bx   = blockIdx.x;
    const int b    = bx >> 4;
    const int i0   = (bx & 15) * TI;
    const int tid  = threadIdx.x;
    const int di   = tid >> 5;
    const int lane = tid & 31;
    const int r    = lane & 3;
    const int jseg = (lane >> 2) * 8;

    const float* xb = x + (size_t)b * CC * HW;
    const float* yb = y + (size_t)b * CC * HW;

    // Valid-row mask for the y tile (rows i0-4 .. i0+7)
    int vmask = 0;
    #pragma unroll
    for (int q = 0; q < YR; ++q) {
        int gi = i0 + q - DD;
        if (gi >= 0 && gi < HH) vmask |= (1 << q);
    }

    // Zero the y regions of BOTH buffers once: halo slots are never rewritten.
    {
        float2* y0 = reinterpret_cast<float2*>(smem + XSZ);
        float2* y1 = reinterpret_cast<float2*>(smem + BUFSZ + XSZ);
        const float2 z = make_float2(0.f, 0.f);
        for (int idx = tid; idx < YSZ / 2; idx += NTH) { y0[idx] = z; y1[idx] = z; }
    }
    __syncthreads();

    float acc[8][PP];
    #pragma unroll
    for (int k = 0; k < 8; ++k)
        #pragma unroll
        for (int d = 0; d < PP; ++d)
            acc[k][d] = 0.0f;

    // Prime the pipeline
    stage_chunk(smem, xb, yb, 0, i0, tid, vmask);
    cp_commit();

    for (int k = 0; k < NCHUNK; ++k) {
        float* cur = smem + (k & 1) * BUFSZ;
        if (k + 1 < NCHUNK) {
            stage_chunk(smem + ((k + 1) & 1) * BUFSZ, xb, yb,
                        (k + 1) * KC, i0, tid, vmask);
            cp_commit();
            asm volatile("cp.async.wait_group 1;\n");
        } else {
            asm volatile("cp.async.wait_group 0;\n");
        }
        __syncthreads();
        compute_chunk(cur, acc, r, di, jseg);
        __syncthreads();
    }

    // Write out: out[b, di*9+d, i0+r, jseg..jseg+7]
    const float scale = 1.0f / (float)CC;
    #pragma unroll
    for (int d = 0; d < PP; ++d) {
        int ch = di * PP + d;
        float* o = out + (((size_t)b * (PP * PP) + ch) * HH + (i0 + r)) * WW + jseg;
        float4 v0, v1;
        v0.x = acc[0][d] * scale; v0.y = acc[1][d] * scale;
        v0.z = acc[2][d] * scale; v0.w = acc[3][d] * scale;
        v1.x = acc[4][d] * scale; v1.y = acc[5][d] * scale;
        v1.z = acc[6][d] * scale; v1.w = acc[7][d] * scale;
        reinterpret_cast<float4*>(o)[0] = v0;
        reinterpret_cast<float4*>(o)[1] = v1;
    }
}

extern "C" void kernel_launch(void* const* d_in, const int* in_sizes, int n_in,
                              void* d_out, int out_size)
{
    const float* x = (const float*)d_in[0];
    const float* y = (const float*)d_in[1];
    float* out = (float*)d_out;
    (void)in_sizes; (void)n_in; (void)out_size;

    cudaFuncSetAttribute(corr_kernel,
                         cudaFuncAttributeMaxDynamicSharedMemorySize, SMEM_BYTES);

    dim3 grid(BB * (HH / TI));   // 256 blocks
    dim3 block(NTH);             // 9 warps
    corr_kernel<<<grid, block, SMEM_BYTES>>>(x, y, out);
}